// round 1
// baseline (speedup 1.0000x reference)
#include <cuda_runtime.h>
#include <cuda_bf16.h>

#define BB 8
#define NN 64
#define DD 64
#define EE 32

// Scratch for the aggregated messages (agg[b, i_node, d]).
__device__ float g_agg[BB * NN * DD];

// ---------------------------------------------------------------------------
// Kernel 1: fused  A = relu(edges @ W_e + b_e);  messages = A @ nodes_j;
//           agg = sum_j(mask * messages)
// One CTA per (b, i_node). 8 warps; warp w computes d = w*8 + dd for dd in 0..7.
// Each lane keeps a 64-float register slice of W_e (2 columns x 32 k),
// reused across all 64 j_node iterations -> inner loop is pure FFMA.
// ---------------------------------------------------------------------------
__global__ void __launch_bounds__(256)
agg_kernel(const float* __restrict__ nodes,
           const float* __restrict__ edges,
           const float* __restrict__ mask,
           const float* __restrict__ W_e,
           const float* __restrict__ b_e)
{
    const int cta = blockIdx.x;        // b*64 + i_node
    const int b   = cta >> 6;
    const int i   = cta & 63;

    __shared__ __align__(16) float edges_s[NN][EE];  // 8 KB
    __shared__ __align__(16) float nodes_s[NN][DD];  // 16 KB
    __shared__ float mask_s[NN];

    const int tid = threadIdx.x;

    // Stage edges for e = i*64 + jn (jn = 0..63)
    const float* eb = edges + ((size_t)b * NN * NN + (size_t)i * NN) * EE;
    for (int idx = tid; idx < NN * EE; idx += 256)
        ((float*)edges_s)[idx] = eb[idx];
    // Stage nodes[b]
    const float* nb = nodes + (size_t)b * NN * DD;
    for (int idx = tid; idx < NN * DD; idx += 256)
        ((float*)nodes_s)[idx] = nb[idx];
    if (tid < NN)
        mask_s[tid] = mask[(size_t)b * NN * NN + (size_t)i * NN + tid];
    __syncthreads();

    const int warp = tid >> 5;
    const int lane = tid & 31;

    for (int dd = 0; dd < 8; dd++) {
        const int d    = warp * 8 + dd;
        const int col0 = d * 64 + lane;

        // Register-resident W_e slice: columns col0 and col0+32, all 32 k.
        float w0[EE], w1[EE];
#pragma unroll
        for (int k = 0; k < EE; k++) {
            w0[k] = __ldg(&W_e[k * 4096 + col0]);
            w1[k] = __ldg(&W_e[k * 4096 + col0 + 32]);
        }
        const float be0 = __ldg(&b_e[col0]);
        const float be1 = __ldg(&b_e[col0 + 32]);

        float acc = 0.f;
        for (int jn = 0; jn < NN; jn++) {
            float dot0 = be0, dot1 = be1;
            const float4* e4 = reinterpret_cast<const float4*>(edges_s[jn]);
#pragma unroll
            for (int kq = 0; kq < EE / 4; kq++) {
                const float4 ev = e4[kq];
                dot0 = fmaf(ev.x, w0[kq * 4 + 0], dot0);
                dot1 = fmaf(ev.x, w1[kq * 4 + 0], dot1);
                dot0 = fmaf(ev.y, w0[kq * 4 + 1], dot0);
                dot1 = fmaf(ev.y, w1[kq * 4 + 1], dot1);
                dot0 = fmaf(ev.z, w0[kq * 4 + 2], dot0);
                dot1 = fmaf(ev.z, w1[kq * 4 + 2], dot1);
                dot0 = fmaf(ev.w, w0[kq * 4 + 3], dot0);
                dot1 = fmaf(ev.w, w1[kq * 4 + 3], dot1);
            }
            const float p = fmaxf(dot0, 0.f) * nodes_s[jn][lane]
                          + fmaxf(dot1, 0.f) * nodes_s[jn][lane + 32];
            acc = fmaf(p, mask_s[jn], acc);
        }

        // Warp-reduce over lanes (j dimension)
#pragma unroll
        for (int off = 16; off; off >>= 1)
            acc += __shfl_xor_sync(0xffffffffu, acc, off);
        if (lane == 0)
            g_agg[cta * 64 + d] = acc;
    }
}

// ---------------------------------------------------------------------------
// Kernel 2: both GRU steps fused. One CTA (64 threads) per row (b*N+n).
// Step 1: h = 0  ->  h1 = (1-z)*tanh(xh + r*b1h)
// Step 2: x = agg, h = h1
// ---------------------------------------------------------------------------
__global__ void __launch_bounds__(64)
gru_kernel(const float* __restrict__ nodes,
           const float* __restrict__ K,
           const float* __restrict__ R,
           const float* __restrict__ bias,
           float* __restrict__ out)
{
    const int row = blockIdx.x;   // b*N + n
    const int d   = threadIdx.x;  // 0..63

    __shared__ float x1s[DD], x2s[DD], h1s[DD];
    x1s[d] = nodes[(size_t)row * DD + d];
    x2s[d] = g_agg[(size_t)row * DD + d];
    __syncthreads();

    const float b0z = bias[d],       b0r = bias[64 + d],  b0h = bias[128 + d];
    const float b1z = bias[192 + d], b1r = bias[256 + d], b1h = bias[320 + d];

    // ---- step 1 (h = 0) ----
    float xz = b0z, xr = b0r, xh = b0h;
#pragma unroll 8
    for (int k = 0; k < DD; k++) {
        const float  xv = x1s[k];
        const float* Kr = K + k * 192;
        xz = fmaf(xv, Kr[d],       xz);
        xr = fmaf(xv, Kr[64 + d],  xr);
        xh = fmaf(xv, Kr[128 + d], xh);
    }
    float z  = 1.f / (1.f + expf(-(xz + b1z)));
    float r  = 1.f / (1.f + expf(-(xr + b1r)));
    float hh = tanhf(xh + r * b1h);
    const float h1 = (1.f - z) * hh;
    h1s[d] = h1;
    __syncthreads();

    // ---- step 2 (x = agg, h = h1) ----
    xz = b0z; xr = b0r; xh = b0h;
    float hz = b1z, hr = b1r, hhl = b1h;
#pragma unroll 8
    for (int k = 0; k < DD; k++) {
        const float  xv = x2s[k];
        const float  hv = h1s[k];
        const float* Kr = K + k * 192;
        const float* Rr = R + k * 192;
        xz  = fmaf(xv, Kr[d],       xz);
        xr  = fmaf(xv, Kr[64 + d],  xr);
        xh  = fmaf(xv, Kr[128 + d], xh);
        hz  = fmaf(hv, Rr[d],       hz);
        hr  = fmaf(hv, Rr[64 + d],  hr);
        hhl = fmaf(hv, Rr[128 + d], hhl);
    }
    z  = 1.f / (1.f + expf(-(xz + hz)));
    r  = 1.f / (1.f + expf(-(xr + hr)));
    hh = tanhf(xh + r * hhl);
    out[(size_t)row * DD + d] = z * h1 + (1.f - z) * hh;
}

// ---------------------------------------------------------------------------
extern "C" void kernel_launch(void* const* d_in, const int* in_sizes, int n_in,
                              void* d_out, int out_size)
{
    const float* nodes  = (const float*)d_in[0];
    const float* edges  = (const float*)d_in[1];
    const float* mask   = (const float*)d_in[2];
    const float* W_e    = (const float*)d_in[3];
    const float* b_e    = (const float*)d_in[4];
    const float* gruK   = (const float*)d_in[5];
    const float* gruR   = (const float*)d_in[6];
    const float* gruB   = (const float*)d_in[7];
    float*       out    = (float*)d_out;

    agg_kernel<<<BB * NN, 256>>>(nodes, edges, mask, W_e, b_e);
    gru_kernel<<<BB * NN, 64>>>(nodes, gruK, gruR, gruB, out);
}

// round 3
// speedup vs baseline: 2.5861x; 2.5861x over previous
#include <cuda_runtime.h>
#include <cuda_bf16.h>

#define BB 8
#define NN 64
#define DD 64
#define EE 32

// ---------------------------------------------------------------------------
// Scratch (device globals; no allocation allowed in kernel_launch)
// ---------------------------------------------------------------------------
__device__ float g_agg[BB * NN * DD];
__device__ __nv_bfloat16 g_Wt_hi[DD * DD * EE];      // [col (4096)][k (32)]
__device__ __nv_bfloat16 g_Wt_lo[DD * DD * EE];
__device__ __nv_bfloat16 g_E_hi[BB * NN * NN * EE];  // [b][e][k] row-major
__device__ __nv_bfloat16 g_E_lo[BB * NN * NN * EE];

// ---------------------------------------------------------------------------
// Prep: split fp32 -> bf16 hi/lo (x = hi + lo exactly to ~2^-17 rel)
// W_e is transposed to [col][k] so B-fragments load contiguous k-pairs.
// ---------------------------------------------------------------------------
__global__ void prep_w_kernel(const float* __restrict__ W_e)
{
    int idx = blockIdx.x * blockDim.x + threadIdx.x;   // over 32*4096
    if (idx >= EE * DD * DD) return;
    int k = idx >> 12;           // / 4096
    int col = idx & 4095;
    float x = W_e[idx];
    __nv_bfloat16 h = __float2bfloat16(x);
    float lo = x - __bfloat162float(h);
    g_Wt_hi[col * EE + k] = h;
    g_Wt_lo[col * EE + k] = __float2bfloat16(lo);
}

__global__ void prep_e_kernel(const float* __restrict__ edges)
{
    int idx = blockIdx.x * blockDim.x + threadIdx.x;   // over 1,048,576
    if (idx >= BB * NN * NN * EE) return;
    float x = edges[idx];
    __nv_bfloat16 h = __float2bfloat16(x);
    float lo = x - __bfloat162float(h);
    g_E_hi[idx] = h;
    g_E_lo[idx] = __float2bfloat16(lo);
}

// ---------------------------------------------------------------------------
// m16n8k16 bf16 mma wrapper
// ---------------------------------------------------------------------------
#define MMA_BF16(C, A, b0, b1)                                                 \
    asm volatile(                                                              \
        "mma.sync.aligned.m16n8k16.row.col.f32.bf16.bf16.f32 "                 \
        "{%0,%1,%2,%3}, {%4,%5,%6,%7}, {%8,%9}, {%0,%1,%2,%3};"                \
        : "+f"((C)[0]), "+f"((C)[1]), "+f"((C)[2]), "+f"((C)[3])               \
        : "r"((A)[0]), "r"((A)[1]), "r"((A)[2]), "r"((A)[3]),                  \
          "r"(b0), "r"(b1))

// ---------------------------------------------------------------------------
// Kernel 1: fused tensor-core version.
// CTA = (b, i_node). Warp w computes agg[d] for d = w*8 .. w*8+7.
// Per d: P (64 j x 64 dp) = relu(Edges(64x32) @ W_e[:, d*64:+64] + bias)
//        agg[d] = sum_{j,dp} P[j,dp] * mask[j]*nodes[j,dp]
// Edges A-fragments (hi+lo) live in registers for the whole kernel.
// 3-pass bf16 split: hi*hi + hi*lo + lo*hi (fp32 accumulate).
// ---------------------------------------------------------------------------
__global__ void __launch_bounds__(256)
agg_kernel(const float* __restrict__ nodes,
           const float* __restrict__ mask,
           const float* __restrict__ b_e)
{
    const int cta = blockIdx.x;    // b*64 + i
    const int b   = cta >> 6;
    const int i   = cta & 63;

    __shared__ float Mn[NN][DD];   // mask[j] * nodes[j][dp], 16 KB
    const int tid = threadIdx.x;
    {
        const float* nb = nodes + (size_t)b * NN * DD;
        const float* mb = mask  + (size_t)b * NN * NN + (size_t)i * NN;
        for (int idx = tid; idx < NN * DD; idx += 256) {
            int j  = idx >> 6;
            int dp = idx & 63;
            Mn[j][dp] = mb[j] * nb[j * DD + dp];
        }
    }
    __syncthreads();

    const int warp = tid >> 5;
    const int lane = tid & 31;
    const int qid  = lane >> 2;    // 0..7
    const int tq   = lane & 3;     // 0..3

    // ---- A fragments (edges for this (b,i)), hi and lo, all k-tiles ----
    const __nv_bfloat16* Eh = g_E_hi + ((size_t)b * NN * NN + (size_t)i * NN) * EE;
    const __nv_bfloat16* El = g_E_lo + ((size_t)b * NN * NN + (size_t)i * NN) * EE;

    unsigned ah[4][2][4], al[4][2][4];
#pragma unroll
    for (int m = 0; m < 4; m++) {
#pragma unroll
        for (int kt = 0; kt < 2; kt++) {
            const int j0 = m * 16 + qid;
            const int k0 = kt * 16 + tq * 2;
            ah[m][kt][0] = *(const unsigned*)(Eh + (size_t)j0 * EE + k0);
            ah[m][kt][1] = *(const unsigned*)(Eh + (size_t)(j0 + 8) * EE + k0);
            ah[m][kt][2] = *(const unsigned*)(Eh + (size_t)j0 * EE + k0 + 8);
            ah[m][kt][3] = *(const unsigned*)(Eh + (size_t)(j0 + 8) * EE + k0 + 8);
            al[m][kt][0] = *(const unsigned*)(El + (size_t)j0 * EE + k0);
            al[m][kt][1] = *(const unsigned*)(El + (size_t)(j0 + 8) * EE + k0);
            al[m][kt][2] = *(const unsigned*)(El + (size_t)j0 * EE + k0 + 8);
            al[m][kt][3] = *(const unsigned*)(El + (size_t)(j0 + 8) * EE + k0 + 8);
        }
    }

    for (int dd = 0; dd < 8; dd++) {
        const int d = warp * 8 + dd;
        float acc = 0.f;

#pragma unroll
        for (int nt = 0; nt < 8; nt++) {
            const int dp0 = nt * 8 + tq * 2;        // C-fragment col base
            const float bias0 = __ldg(&b_e[d * 64 + dp0]);
            const float bias1 = __ldg(&b_e[d * 64 + dp0 + 1]);

            float c[4][4];
#pragma unroll
            for (int m = 0; m < 4; m++) {
                c[m][0] = bias0; c[m][1] = bias1;
                c[m][2] = bias0; c[m][3] = bias1;
            }

#pragma unroll
            for (int kt = 0; kt < 2; kt++) {
                const int ncol = d * 64 + nt * 8 + qid;   // B-fragment col
                const int koff = kt * 16 + tq * 2;
                const __nv_bfloat16* wh = g_Wt_hi + (size_t)ncol * EE + koff;
                const __nv_bfloat16* wl = g_Wt_lo + (size_t)ncol * EE + koff;
                const unsigned bh0 = *(const unsigned*)wh;
                const unsigned bh1 = *(const unsigned*)(wh + 8);
                const unsigned bl0 = *(const unsigned*)wl;
                const unsigned bl1 = *(const unsigned*)(wl + 8);

#pragma unroll
                for (int m = 0; m < 4; m++) {
                    MMA_BF16(c[m], ah[m][kt], bh0, bh1);
                    MMA_BF16(c[m], ah[m][kt], bl0, bl1);
                    MMA_BF16(c[m], al[m][kt], bh0, bh1);
                }
            }

            // epilogue: relu, multiply by mask*nodes, accumulate scalar
#pragma unroll
            for (int m = 0; m < 4; m++) {
                const int j0 = m * 16 + qid;
                const float2 mn0 = *(const float2*)&Mn[j0][dp0];
                const float2 mn1 = *(const float2*)&Mn[j0 + 8][dp0];
                acc = fmaf(fmaxf(c[m][0], 0.f), mn0.x, acc);
                acc = fmaf(fmaxf(c[m][1], 0.f), mn0.y, acc);
                acc = fmaf(fmaxf(c[m][2], 0.f), mn1.x, acc);
                acc = fmaf(fmaxf(c[m][3], 0.f), mn1.y, acc);
            }
        }

        // warp allreduce (j and dp both fully covered inside the warp)
#pragma unroll
        for (int off = 16; off; off >>= 1)
            acc += __shfl_xor_sync(0xffffffffu, acc, off);
        if (lane == 0)
            g_agg[cta * 64 + d] = acc;
    }
}

// ---------------------------------------------------------------------------
// Kernel 2: both GRU steps fused; 4 rows per CTA for occupancy/latency hiding.
// ---------------------------------------------------------------------------
__global__ void __launch_bounds__(256)
gru_kernel(const float* __restrict__ nodes,
           const float* __restrict__ K,
           const float* __restrict__ R,
           const float* __restrict__ bias,
           float* __restrict__ out)
{
    const int ry  = threadIdx.y;               // 0..3
    const int row = blockIdx.x * 4 + ry;       // b*N + n
    const int d   = threadIdx.x;               // 0..63

    __shared__ float x1s[4][DD], x2s[4][DD], h1s[4][DD];
    x1s[ry][d] = nodes[(size_t)row * DD + d];
    x2s[ry][d] = g_agg[(size_t)row * DD + d];
    __syncthreads();

    const float b0z = bias[d],       b0r = bias[64 + d],  b0h = bias[128 + d];
    const float b1z = bias[192 + d], b1r = bias[256 + d], b1h = bias[320 + d];

    // ---- step 1 (h = 0) ----
    float xz = b0z, xr = b0r, xh = b0h;
#pragma unroll 8
    for (int k = 0; k < DD; k++) {
        const float  xv = x1s[ry][k];
        const float* Kr = K + k * 192;
        xz = fmaf(xv, Kr[d],       xz);
        xr = fmaf(xv, Kr[64 + d],  xr);
        xh = fmaf(xv, Kr[128 + d], xh);
    }
    float z  = 1.f / (1.f + expf(-(xz + b1z)));
    float r  = 1.f / (1.f + expf(-(xr + b1r)));
    float hh = tanhf(xh + r * b1h);
    const float h1 = (1.f - z) * hh;
    h1s[ry][d] = h1;
    __syncthreads();

    // ---- step 2 (x = agg, h = h1) ----
    xz = b0z; xr = b0r; xh = b0h;
    float hz = b1z, hr = b1r, hhl = b1h;
#pragma unroll 8
    for (int k = 0; k < DD; k++) {
        const float  xv = x2s[ry][k];
        const float  hv = h1s[ry][k];
        const float* Kr = K + k * 192;
        const float* Rr = R + k * 192;
        xz  = fmaf(xv, Kr[d],       xz);
        xr  = fmaf(xv, Kr[64 + d],  xr);
        xh  = fmaf(xv, Kr[128 + d], xh);
        hz  = fmaf(hv, Rr[d],       hz);
        hr  = fmaf(hv, Rr[64 + d],  hr);
        hhl = fmaf(hv, Rr[128 + d], hhl);
    }
    z  = 1.f / (1.f + expf(-(xz + hz)));
    r  = 1.f / (1.f + expf(-(xr + hr)));
    hh = tanhf(xh + r * hhl);
    out[(size_t)row * DD + d] = z * h1 + (1.f - z) * hh;
}

// ---------------------------------------------------------------------------
extern "C" void kernel_launch(void* const* d_in, const int* in_sizes, int n_in,
                              void* d_out, int out_size)
{
    const float* nodes  = (const float*)d_in[0];
    const float* edges  = (const float*)d_in[1];
    const float* mask   = (const float*)d_in[2];
    const float* W_e    = (const float*)d_in[3];
    const float* b_e    = (const float*)d_in[4];
    const float* gruK   = (const float*)d_in[5];
    const float* gruR   = (const float*)d_in[6];
    const float* gruB   = (const float*)d_in[7];
    float*       out    = (float*)d_out;

    prep_w_kernel<<<(EE * DD * DD + 255) / 256, 256>>>(W_e);
    prep_e_kernel<<<(BB * NN * NN * EE + 255) / 256, 256>>>(edges);
    agg_kernel<<<BB * NN, 256>>>(nodes, mask, b_e);
    gru_kernel<<<BB * NN / 4, dim3(64, 4)>>>(nodes, gruK, gruR, gruB, out);
}